// round 10
// baseline (speedup 1.0000x reference)
#include <cuda_runtime.h>
#include <math.h>
#include <stdint.h>

// Problem constants
#define TT  2048
#define EE  1024
#define HH  16
#define DHD 64
#define FFD 4096
#define VV  32000
#define NL  4

#define INV254 (1.0f / 254.0f)

// ---------------------------------------------------------------------------
// Scratch (device globals)
// ---------------------------------------------------------------------------
__device__ __align__(128) float g_x   [TT * EE];
__device__ __align__(128) float g_qkv [TT * 3 * EE];
__device__ __align__(128) float g_att [TT * EE];
__device__ __align__(128) float g_f   [TT * FFD];
__device__ __align__(128) float g_bqkv[NL * 3 * EE];

__device__ __align__(128) int8_t g_aq [TT * 2 * EE];     // act hi|lo (pitch 2E)
__device__ __align__(128) int8_t g_fq [TT * 2 * FFD];
__device__ float g_sa[TT];
__device__ float g_sf[TT];

__device__ __align__(128) int8_t g_wqkvq[(size_t)NL * 3 * EE * 2 * EE];
__device__ __align__(128) int8_t g_woq  [(size_t)NL * EE * 2 * EE];
__device__ __align__(128) int8_t g_w1q  [(size_t)NL * FFD * 2 * EE];
__device__ __align__(128) int8_t g_w2q  [(size_t)NL * EE * 2 * FFD];
__device__ __align__(128) int8_t g_whq  [(size_t)VV * 2 * EE];
__device__ float g_sqkv[NL * 3 * EE];
__device__ float g_swo [NL * EE];
__device__ float g_sw1 [NL * FFD];
__device__ float g_sw2 [NL * EE];
__device__ float g_swh [VV];

// ---------------------------------------------------------------------------
// Helpers
// ---------------------------------------------------------------------------
__device__ __forceinline__ uint32_t smem_u32(const void* p) {
    uint32_t a;
    asm("{ .reg .u64 t; cvta.to.shared.u64 t, %1; cvt.u32.u64 %0, t; }" : "=r"(a) : "l"(p));
    return a;
}

#define CP_ASYNC16(saddr, gptr) \
    asm volatile("cp.async.cg.shared.global [%0], [%1], 16;" \
        :: "r"(saddr), "l"(gptr) : "memory")
#define CP_COMMIT() asm volatile("cp.async.commit_group;" ::: "memory")
#define CP_WAIT(N)  asm volatile("cp.async.wait_group %0;" :: "n"(N) : "memory")

#define LDSM4(r0, r1, r2, r3, addr) \
    asm volatile("ldmatrix.sync.aligned.m8n8.x4.shared.b16 {%0,%1,%2,%3}, [%4];" \
        : "=r"(r0), "=r"(r1), "=r"(r2), "=r"(r3) : "r"(addr))

#define MMAS8(d, a, b) \
    asm volatile("mma.sync.aligned.m16n8k32.row.col.s32.s8.s8.s32 " \
        "{%0,%1,%2,%3}, {%4,%5,%6,%7}, {%8,%9}, {%0,%1,%2,%3};" \
        : "+r"((d)[0]), "+r"((d)[1]), "+r"((d)[2]), "+r"((d)[3]) \
        : "r"((a)[0]), "r"((a)[1]), "r"((a)[2]), "r"((a)[3]), \
          "r"((b)[0]), "r"((b)[1]))

__device__ __forceinline__ float gelu_erf(float v) {
    return 0.5f * v * (1.0f + erff(v * 0.70710678118654752f));
}

__device__ __forceinline__ float block_max(float v, float* sm8) {
    #pragma unroll
    for (int off = 16; off > 0; off >>= 1)
        v = fmaxf(v, __shfl_xor_sync(0xffffffffu, v, off));
    int w = threadIdx.x >> 5;
    if ((threadIdx.x & 31) == 0) sm8[w] = v;
    __syncthreads();
    float r = fmaxf(fmaxf(fmaxf(sm8[0], sm8[1]), fmaxf(sm8[2], sm8[3])),
                    fmaxf(fmaxf(sm8[4], sm8[5]), fmaxf(sm8[6], sm8[7])));
    return r;
}

__device__ __forceinline__ void quant4(float4 v, float invs, char4& hi, char4& lo) {
    float q0 = rintf(v.x * invs), q1 = rintf(v.y * invs);
    float q2 = rintf(v.z * invs), q3 = rintf(v.w * invs);
    hi = make_char4((char)(int)q0, (char)(int)q1, (char)(int)q2, (char)(int)q3);
    lo = make_char4((char)(int)rintf((v.x * invs - q0) * 254.0f),
                    (char)(int)rintf((v.y * invs - q1) * 254.0f),
                    (char)(int)rintf((v.z * invs - q2) * 254.0f),
                    (char)(int)rintf((v.w * invs - q3) * 254.0f));
}

// ---------------------------------------------------------------------------
// Embedding
// ---------------------------------------------------------------------------
__global__ void embed_kernel(const int* __restrict__ ids,
                             const float* __restrict__ tok,
                             const float* __restrict__ pos,
                             float* __restrict__ x) {
    int t = blockIdx.x;
    int c = threadIdx.x * 4;
    int id = ids[t];
    float4 a = *(const float4*)(tok + (size_t)id * EE + c);
    float4 b = *(const float4*)(pos + (size_t)t * EE + c);
    a.x += b.x; a.y += b.y; a.z += b.z; a.w += b.w;
    *(float4*)(x + (size_t)t * EE + c) = a;
}

// ---------------------------------------------------------------------------
// LayerNorm fused with 2-digit int8 row quantization.
// ---------------------------------------------------------------------------
__global__ void ln_quant_kernel(const float* __restrict__ x,
                                const float* __restrict__ g,
                                const float* __restrict__ b,
                                int8_t* __restrict__ out,
                                float* __restrict__ scale) {
    int t = blockIdx.x;
    int c = threadIdx.x * 4;
    float4 v4 = *(const float4*)(x + (size_t)t * EE + c);
    float s = v4.x + v4.y + v4.z + v4.w;
    float q = v4.x * v4.x + v4.y * v4.y + v4.z * v4.z + v4.w * v4.w;
    #pragma unroll
    for (int off = 16; off > 0; off >>= 1) {
        s += __shfl_down_sync(0xffffffffu, s, off);
        q += __shfl_down_sync(0xffffffffu, q, off);
    }
    __shared__ float ss[8], qq[8], mm[8];
    __shared__ float mean_s, rstd_s;
    int w = threadIdx.x >> 5, lane = threadIdx.x & 31;
    if (lane == 0) { ss[w] = s; qq[w] = q; }
    __syncthreads();
    if (threadIdx.x == 0) {
        float S = 0.f, Q = 0.f;
        #pragma unroll
        for (int i = 0; i < 8; i++) { S += ss[i]; Q += qq[i]; }
        float m = S * (1.0f / EE);
        float var = Q * (1.0f / EE) - m * m;
        mean_s = m;
        rstd_s = rsqrtf(var + 1e-5f);
    }
    __syncthreads();
    float m = mean_s, r = rstd_s;
    float4 gg = *(const float4*)(g + c);
    float4 bb = *(const float4*)(b + c);
    float4 o;
    o.x = (v4.x - m) * r * gg.x + bb.x;
    o.y = (v4.y - m) * r * gg.y + bb.y;
    o.z = (v4.z - m) * r * gg.z + bb.z;
    o.w = (v4.w - m) * r * gg.w + bb.w;
    float amax = fmaxf(fmaxf(fabsf(o.x), fabsf(o.y)), fmaxf(fabsf(o.z), fabsf(o.w)));
    amax = fmaxf(block_max(amax, mm), 1e-20f);
    float invs = 127.0f / amax;
    char4 hi, lo;
    quant4(o, invs, hi, lo);
    int8_t* d = out + (size_t)t * 2 * EE;
    *(char4*)(d + c) = hi;
    *(char4*)(d + EE + c) = lo;
    if (threadIdx.x == 0) scale[t] = amax * (1.0f / 127.0f);
}

// ---------------------------------------------------------------------------
// Warp-per-row 2-digit int8 quantization (weights or activations).
// 256 threads = 8 rows per CTA. Two reads of the row (2nd is L1/L2 hot).
// Row remap: src row -> dst row l*dstStrideL + dstOff + e (pitch 2K).
// ---------------------------------------------------------------------------
template <int K>
__global__ void quantw_kernel(const float* __restrict__ src,
                              int8_t* __restrict__ dst,
                              float* __restrict__ scale,
                              int rowsPerL, int dstStrideL, int dstOff,
                              int totalRows) {
    int row = blockIdx.x * 8 + (threadIdx.x >> 5);
    if (row >= totalRows) return;
    int lane = threadIdx.x & 31;
    int l = row / rowsPerL;
    int e = row - l * rowsPerL;
    size_t drow = (size_t)l * dstStrideL + dstOff + e;
    const float* sp = src + (size_t)row * K;
    constexpr int NV = K / 128;   // float4 per lane

    float amax = 0.f;
    #pragma unroll 4
    for (int i = 0; i < NV; i++) {
        float4 v = *(const float4*)(sp + (size_t)(lane + i * 32) * 4);
        amax = fmaxf(amax, fmaxf(fmaxf(fabsf(v.x), fabsf(v.y)),
                                 fmaxf(fabsf(v.z), fabsf(v.w))));
    }
    #pragma unroll
    for (int off = 16; off > 0; off >>= 1)
        amax = fmaxf(amax, __shfl_xor_sync(0xffffffffu, amax, off));
    amax = fmaxf(amax, 1e-20f);
    float invs = 127.0f / amax;

    int8_t* d = dst + drow * (size_t)(2 * K);
    #pragma unroll 4
    for (int i = 0; i < NV; i++) {
        int c = (lane + i * 32) * 4;
        float4 v = *(const float4*)(sp + c);
        char4 hi, lo;
        quant4(v, invs, hi, lo);
        *(char4*)(d + c) = hi;
        *(char4*)(d + K + c) = lo;
    }
    if (lane == 0) scale[drow] = amax * (1.0f / 127.0f);
}

__global__ void pack_bias_kernel(const float* __restrict__ bq,
                                 const float* __restrict__ bk,
                                 const float* __restrict__ bv,
                                 float* __restrict__ dst) {
    int i = blockIdx.x * 256 + threadIdx.x;
    if (i >= NL * 3 * EE) return;
    int l = i / (3 * EE);
    int r = i - l * 3 * EE;
    float v = (r < EE) ? bq[l * EE + r]
            : (r < 2 * EE) ? bk[l * EE + r - EE]
            : bv[l * EE + r - 2 * EE];
    dst[i] = v;
}

// ---------------------------------------------------------------------------
// int8 pass-fused NT GEMM via mma.sync m16n8k32 (A-reuse form):
//   Pass1 (it < nKp): chunk {A_hi, B_hi, B_lo}: acc1 += Ah*Bh, acc2 += Ah*Bl
//   Pass2          : chunk {A_lo, B_hi}:        acc2 += Al*Bh
//   C = sA[m]*sB[n]*(acc1 + acc2/254)  (+ epilogue)
// Template: BM, BN, TH(threads), EPI, MINB. Warp grid (TH/128) x 4.
// EPI: 0 none, 1 +bias, 2 +bias+res, 3 +bias then erf-GELU
// ---------------------------------------------------------------------------
template <int BM, int BN, int TH, int EPI, int MINB>
__global__ void __launch_bounds__(TH, MINB)
igemm_kernel(const int8_t* __restrict__ A,
             const int8_t* __restrict__ B,
             const float* __restrict__ sAv,
             const float* __restrict__ sBv,
             const float* __restrict__ bias,
             const float* __restrict__ res,
             float* __restrict__ C,
             int K, int ldc) {
    constexpr int WMC = TH / 128;      // warps along M (2 or 4)
    constexpr int WM  = BM / WMC;      // 64
    constexpr int MT  = WM / 16;       // 4
    constexpr int WN  = BN / 4;        // 32 or 16
    constexpr int NT  = WN / 8;        // 4 or 2
    constexpr int STRIDE = 144;
    constexpr int A_BYTES = BM * STRIDE;
    constexpr int B_BYTES = BN * STRIDE;
    constexpr int SLOT    = A_BYTES + 2 * B_BYTES;

    extern __shared__ char smem[];
    const uint32_t sbase = smem_u32(smem);
    const int tid = threadIdx.x;
    const int wid = tid >> 5;
    const int lane = tid & 31;
    const int warp_m = wid & (WMC - 1);
    const int warp_n = wid / WMC;
    const int brow = blockIdx.x * BM;
    const int bcol = blockIdx.y * BN;
    const int K2 = 2 * K;
    const int nKp = K >> 7;
    const int nIt = 2 * nKp;

    int acc1[MT][NT][4];
    int acc2[MT][NT][4];
    #pragma unroll
    for (int mt = 0; mt < MT; mt++)
        #pragma unroll
        for (int nt = 0; nt < NT; nt++)
            #pragma unroll
            for (int e = 0; e < 4; e++) { acc1[mt][nt][e] = 0; acc2[mt][nt][e] = 0; }

    auto load_chunk = [&](int slot, int it) {
        uint32_t s0 = sbase + slot * SLOT;
        bool p1 = (it < nKp);
        int kc128 = p1 ? it : (it - nKp);
        int aOff = (p1 ? 0 : K) + kc128 * 128;
        int bOff = kc128 * 128;
        #pragma unroll
        for (int i = 0; i < BM * 8 / TH; i++) {
            int c = tid + i * TH;
            int r = c >> 3, kc = c & 7;
            CP_ASYNC16(s0 + r * STRIDE + kc * 16,
                       A + (size_t)(brow + r) * K2 + aOff + kc * 16);
        }
        uint32_t sB1 = s0 + A_BYTES;
        #pragma unroll
        for (int i = 0; i < BN * 8 / TH; i++) {
            int c = tid + i * TH;
            int r = c >> 3, kc = c & 7;
            CP_ASYNC16(sB1 + r * STRIDE + kc * 16,
                       B + (size_t)(bcol + r) * K2 + bOff + kc * 16);
        }
        if (p1) {
            uint32_t sB2 = s0 + A_BYTES + B_BYTES;
            #pragma unroll
            for (int i = 0; i < BN * 8 / TH; i++) {
                int c = tid + i * TH;
                int r = c >> 3, kc = c & 7;
                CP_ASYNC16(sB2 + r * STRIDE + kc * 16,
                           B + (size_t)(bcol + r) * K2 + K + bOff + kc * 16);
            }
        }
        CP_COMMIT();
    };

    load_chunk(0, 0);
    load_chunk(1, 1);

    int st = 0;
    for (int it = 0; it < nIt; it++) {
        CP_WAIT(1);
        __syncthreads();
        const uint32_t s0 = sbase + st * SLOT;
        const uint32_t aAddr  = s0 + (uint32_t)(warp_m * WM + (lane & 15)) * STRIDE
                                   + (uint32_t)(lane >> 4) * 16;
        const uint32_t bAddr1 = s0 + A_BYTES
                                   + (uint32_t)(warp_n * WN + ((lane >> 4) << 3) + (lane & 7)) * STRIDE
                                   + (uint32_t)((lane >> 3) & 1) * 16;
        const uint32_t bAddr2 = bAddr1 + B_BYTES;
        const bool p1 = (it < nKp);

        if (it + 2 < nIt) {
            int st2 = st + 2; if (st2 >= 3) st2 -= 3;
            load_chunk(st2, it + 2);
        } else {
            CP_COMMIT();
        }

        #pragma unroll
        for (int ks = 0; ks < 4; ks++) {
            uint32_t af[MT][4];
            #pragma unroll
            for (int mt = 0; mt < MT; mt++)
                LDSM4(af[mt][0], af[mt][1], af[mt][2], af[mt][3],
                      aAddr + (uint32_t)(mt * 16 * STRIDE) + (uint32_t)(ks * 32));
            uint32_t bf1[NT][2];
            #pragma unroll
            for (int p = 0; p < NT / 2; p++) {
                uint32_t r0, r1, r2, r3;
                LDSM4(r0, r1, r2, r3,
                      bAddr1 + (uint32_t)(p * 16 * STRIDE) + (uint32_t)(ks * 32));
                bf1[2 * p][0] = r0; bf1[2 * p][1] = r1;
                bf1[2 * p + 1][0] = r2; bf1[2 * p + 1][1] = r3;
            }
            if (p1) {
                #pragma unroll
                for (int mt = 0; mt < MT; mt++)
                    #pragma unroll
                    for (int nt = 0; nt < NT; nt++)
                        MMAS8(acc1[mt][nt], af[mt], bf1[nt]);
                uint32_t bf2[NT][2];
                #pragma unroll
                for (int p = 0; p < NT / 2; p++) {
                    uint32_t r0, r1, r2, r3;
                    LDSM4(r0, r1, r2, r3,
                          bAddr2 + (uint32_t)(p * 16 * STRIDE) + (uint32_t)(ks * 32));
                    bf2[2 * p][0] = r0; bf2[2 * p][1] = r1;
                    bf2[2 * p + 1][0] = r2; bf2[2 * p + 1][1] = r3;
                }
                #pragma unroll
                for (int mt = 0; mt < MT; mt++)
                    #pragma unroll
                    for (int nt = 0; nt < NT; nt++)
                        MMAS8(acc2[mt][nt], af[mt], bf2[nt]);
            } else {
                #pragma unroll
                for (int mt = 0; mt < MT; mt++)
                    #pragma unroll
                    for (int nt = 0; nt < NT; nt++)
                        MMAS8(acc2[mt][nt], af[mt], bf1[nt]);
            }
        }

        st++; if (st == 3) st = 0;
    }

    // ---- epilogue ----
    #pragma unroll
    for (int mt = 0; mt < MT; mt++) {
        const int r0 = brow + warp_m * WM + mt * 16 + (lane >> 2);
        const float sa0 = sAv[r0];
        const float sa1 = sAv[r0 + 8];
        #pragma unroll
        for (int nt = 0; nt < NT; nt++) {
            const int col = bcol + warp_n * WN + nt * 8 + ((lane & 3) << 1);
            float2 sb = *(const float2*)(sBv + col);
            float2 v0, v1;
            v0.x = ((float)acc1[mt][nt][0] + (float)acc2[mt][nt][0] * INV254) * sa0 * sb.x;
            v0.y = ((float)acc1[mt][nt][1] + (float)acc2[mt][nt][1] * INV254) * sa0 * sb.y;
            v1.x = ((float)acc1[mt][nt][2] + (float)acc2[mt][nt][2] * INV254) * sa1 * sb.x;
            v1.y = ((float)acc1[mt][nt][3] + (float)acc2[mt][nt][3] * INV254) * sa1 * sb.y;
            if (EPI >= 1) {
                float2 bb = *(const float2*)(bias + col);
                v0.x += bb.x; v0.y += bb.y;
                v1.x += bb.x; v1.y += bb.y;
            }
            if (EPI == 2) {
                float2 q0 = *(const float2*)(res + (size_t)r0 * ldc + col);
                float2 q1 = *(const float2*)(res + (size_t)(r0 + 8) * ldc + col);
                v0.x += q0.x; v0.y += q0.y;
                v1.x += q1.x; v1.y += q1.y;
            }
            if (EPI == 3) {
                v0.x = gelu_erf(v0.x); v0.y = gelu_erf(v0.y);
                v1.x = gelu_erf(v1.x); v1.y = gelu_erf(v1.y);
            }
            *(float2*)(C + (size_t)r0 * ldc + col) = v0;
            *(float2*)(C + (size_t)(r0 + 8) * ldc + col) = v1;
        }
    }
}

// ---------------------------------------------------------------------------
// Fused causal attention v2 (KV-split halves), fp32 in/out.
// ---------------------------------------------------------------------------
__global__ void __launch_bounds__(128)
attn_kernel(const float* __restrict__ q,
            const float* __restrict__ k,
            const float* __restrict__ v,
            float* __restrict__ o, int qp) {
    __shared__ float Ks[2][16][64];
    __shared__ float Vs[2][16][64];
    __shared__ float comb[64][66];

    const int h    = blockIdx.y;
    const int qt   = (int)gridDim.x - 1 - blockIdx.x;   // LPT
    const int half = threadIdx.x >> 6;
    const int lt   = threadIdx.x & 63;
    const int iq   = qt * 64 + lt;
    const float scale = 0.125f;

    const int nTiles = qt * 4 + 4;
    const int split  = nTiles >> 1;
    const int t0 = half ? split : 0;
    const int t1 = half ? nTiles : split;

    float qr[64];
    {
        const float* qptr = q + (size_t)iq * qp + h * DHD;
        #pragma unroll
        for (int d = 0; d < 64; d += 4) {
            float4 t4 = *(const float4*)(qptr + d);
            qr[d] = t4.x; qr[d + 1] = t4.y; qr[d + 2] = t4.z; qr[d + 3] = t4.w;
        }
    }

    float m = -INFINITY, l = 0.0f;
    float oacc[64];
    #pragma unroll
    for (int d = 0; d < 64; d++) oacc[d] = 0.0f;

    for (int tile = t0; tile < t1; tile++) {
        const int jt = tile * 16;
        #pragma unroll
        for (int pp = 0; pp < 4; pp++) {
            int f  = lt + pp * 64;
            int r  = f >> 4;
            int c4 = (f & 15) << 2;
            *(float4*)&Ks[half][r][c4] = *(const float4*)(k + (size_t)(jt + r) * qp + h * DHD + c4);
            *(float4*)&Vs[half][r][c4] = *(const float4*)(v + (size_t)(jt + r) * qp + h * DHD + c4);
        }
        asm volatile("bar.sync %0, 64;" :: "r"(1 + half) : "memory");

        if (jt <= iq) {
            float s[16];
            #pragma unroll
            for (int jj = 0; jj < 16; jj++) {
                float s0 = 0.f, s1 = 0.f, s2 = 0.f, s3 = 0.f;
                #pragma unroll
                for (int d4 = 0; d4 < 16; d4++) {
                    float4 kv = *(const float4*)&Ks[half][jj][d4 * 4];
                    s0 += qr[d4 * 4 + 0] * kv.x;
                    s1 += qr[d4 * 4 + 1] * kv.y;
                    s2 += qr[d4 * 4 + 2] * kv.z;
                    s3 += qr[d4 * 4 + 3] * kv.w;
                }
                float sv = (s0 + s1) + (s2 + s3);
                s[jj] = (jt + jj <= iq) ? sv * scale : -INFINITY;
            }
            float tm = s[0];
            #pragma unroll
            for (int jj = 1; jj < 16; jj++) tm = fmaxf(tm, s[jj]);
            float nm = fmaxf(m, tm);
            float corr = __expf(m - nm);
            l *= corr;
            #pragma unroll
            for (int d = 0; d < 64; d++) oacc[d] *= corr;
            #pragma unroll
            for (int jj = 0; jj < 16; jj++) {
                float pwt = __expf(s[jj] - nm);
                l += pwt;
                #pragma unroll
                for (int d4 = 0; d4 < 16; d4++) {
                    float4 vv = *(const float4*)&Vs[half][jj][d4 * 4];
                    oacc[d4 * 4 + 0] += pwt * vv.x;
                    oacc[d4 * 4 + 1] += pwt * vv.y;
                    oacc[d4 * 4 + 2] += pwt * vv.z;
                    oacc[d4 * 4 + 3] += pwt * vv.w;
                }
            }
            m = nm;
        }
        asm volatile("bar.sync %0, 64;" :: "r"(1 + half) : "memory");
    }

    if (half) {
        #pragma unroll
        for (int d = 0; d < 64; d++) comb[lt][d] = oacc[d];
        comb[lt][64] = m;
        comb[lt][65] = l;
    }
    __syncthreads();
    if (!half) {
        float m1 = comb[lt][64], l1 = comb[lt][65];
        float nm = fmaxf(m, m1);
        float c0 = __expf(m - nm);
        float c1 = __expf(m1 - nm);
        float inv = 1.0f / (l * c0 + l1 * c1);
        float* optr = o + (size_t)iq * EE + h * DHD;
        #pragma unroll
        for (int d = 0; d < 64; d += 4) {
            float4 t4;
            t4.x = (oacc[d]     * c0 + comb[lt][d]     * c1) * inv;
            t4.y = (oacc[d + 1] * c0 + comb[lt][d + 1] * c1) * inv;
            t4.z = (oacc[d + 2] * c0 + comb[lt][d + 2] * c1) * inv;
            t4.w = (oacc[d + 3] * c0 + comb[lt][d + 3] * c1) * inv;
            *(float4*)(optr + d) = t4;
        }
    }
}

// ---------------------------------------------------------------------------
// Host-side launch sequence
// ---------------------------------------------------------------------------
template <int BM, int BN, int TH, int EPI, int MINB>
static inline void igemm(const int8_t* A, const int8_t* B,
                         const float* sA, const float* sB,
                         const float* bias, const float* res, float* C,
                         int M, int N, int K) {
    constexpr int SMEM = 3 * (BM + 2 * BN) * 144;
    dim3 grid(M / BM, N / BN);
    igemm_kernel<BM, BN, TH, EPI, MINB><<<grid, TH, SMEM>>>(A, B, sA, sB, bias, res, C, K, N);
}

extern "C" void kernel_launch(void* const* d_in, const int* in_sizes, int n_in,
                              void* d_out, int out_size) {
    const int*   ids  = (const int*)  d_in[0];
    const float* tok  = (const float*)d_in[1];
    const float* pos  = (const float*)d_in[2];
    const float* Wq   = (const float*)d_in[3];
    const float* bq   = (const float*)d_in[4];
    const float* Wk   = (const float*)d_in[5];
    const float* bk   = (const float*)d_in[6];
    const float* Wv   = (const float*)d_in[7];
    const float* bv   = (const float*)d_in[8];
    const float* Wo   = (const float*)d_in[9];
    const float* bo   = (const float*)d_in[10];
    const float* ln1g = (const float*)d_in[11];
    const float* ln1b = (const float*)d_in[12];
    const float* W1   = (const float*)d_in[13];
    const float* b1   = (const float*)d_in[14];
    const float* W2   = (const float*)d_in[15];
    const float* b2   = (const float*)d_in[16];
    const float* ln2g = (const float*)d_in[17];
    const float* ln2b = (const float*)d_in[18];
    const float* lnfg = (const float*)d_in[19];
    const float* lnfb = (const float*)d_in[20];
    const float* Wh   = (const float*)d_in[21];
    float* out = (float*)d_out;

    // big-tile GEMMs: 3 * (256 + 256) * 144 = 221184 B
    cudaFuncSetAttribute(igemm_kernel<256, 128, 512, 0, 1>, cudaFuncAttributeMaxDynamicSharedMemorySize, 221184);
    cudaFuncSetAttribute(igemm_kernel<256, 128, 512, 1, 1>, cudaFuncAttributeMaxDynamicSharedMemorySize, 221184);
    cudaFuncSetAttribute(igemm_kernel<256, 128, 512, 3, 1>, cudaFuncAttributeMaxDynamicSharedMemorySize, 221184);
    // 128x128 GEMMs: 3 * 384 * 144 = 165888 B
    cudaFuncSetAttribute(igemm_kernel<128, 128, 256, 2, 1>, cudaFuncAttributeMaxDynamicSharedMemorySize, 165888);

    float *x, *qkv, *att, *f, *bqkv, *sa, *sf;
    float *sqkv, *swo, *sw1, *sw2, *swh;
    int8_t *aq, *fq, *wqkvq, *woq, *w1q, *w2q, *whq;
    cudaGetSymbolAddress((void**)&x,     g_x);
    cudaGetSymbolAddress((void**)&qkv,   g_qkv);
    cudaGetSymbolAddress((void**)&att,   g_att);
    cudaGetSymbolAddress((void**)&f,     g_f);
    cudaGetSymbolAddress((void**)&bqkv,  g_bqkv);
    cudaGetSymbolAddress((void**)&aq,    g_aq);
    cudaGetSymbolAddress((void**)&fq,    g_fq);
    cudaGetSymbolAddress((void**)&sa,    g_sa);
    cudaGetSymbolAddress((void**)&sf,    g_sf);
    cudaGetSymbolAddress((void**)&wqkvq, g_wqkvq);
    cudaGetSymbolAddress((void**)&woq,   g_woq);
    cudaGetSymbolAddress((void**)&w1q,   g_w1q);
    cudaGetSymbolAddress((void**)&w2q,   g_w2q);
    cudaGetSymbolAddress((void**)&whq,   g_whq);
    cudaGetSymbolAddress((void**)&sqkv,  g_sqkv);
    cudaGetSymbolAddress((void**)&swo,   g_swo);
    cudaGetSymbolAddress((void**)&sw1,   g_sw1);
    cudaGetSymbolAddress((void**)&sw2,   g_sw2);
    cudaGetSymbolAddress((void**)&swh,   g_swh);

    // ---- up-front weight quantization (warp-per-row) ----
    quantw_kernel<EE><<<(NL * EE + 7) / 8, 256>>>(Wq, wqkvq, sqkv, EE, 3 * EE, 0, NL * EE);
    quantw_kernel<EE><<<(NL * EE + 7) / 8, 256>>>(Wk, wqkvq, sqkv, EE, 3 * EE, EE, NL * EE);
    quantw_kernel<EE><<<(NL * EE + 7) / 8, 256>>>(Wv, wqkvq, sqkv, EE, 3 * EE, 2 * EE, NL * EE);
    quantw_kernel<EE><<<(NL * EE + 7) / 8, 256>>>(Wo, woq, swo, NL * EE, 0, 0, NL * EE);
    quantw_kernel<EE><<<(NL * FFD + 7) / 8, 256>>>(W1, w1q, sw1, NL * FFD, 0, 0, NL * FFD);
    quantw_kernel<FFD><<<(NL * EE + 7) / 8, 256>>>(W2, w2q, sw2, NL * EE, 0, 0, NL * EE);
    quantw_kernel<EE><<<(VV + 7) / 8, 256>>>(Wh, whq, swh, VV, 0, 0, VV);
    pack_bias_kernel<<<(NL * 3 * EE + 255) / 256, 256>>>(bq, bk, bv, bqkv);

    embed_kernel<<<TT, 256>>>(ids, tok, pos, x);

    for (int l = 0; l < NL; l++) {
        const size_t wq_off = (size_t)l * 3 * EE * 2 * EE;
        const size_t wo_off = (size_t)l * EE * 2 * EE;
        const size_t w1_off = (size_t)l * FFD * 2 * EE;
        const size_t w2_off = (size_t)l * EE * 2 * FFD;

        // ---- attention block ----
        ln_quant_kernel<<<TT, 256>>>(x, ln1g + (size_t)l * EE, ln1b + (size_t)l * EE, aq, sa);
        igemm<256, 128, 512, 1, 1>(aq, wqkvq + wq_off, sa, sqkv + (size_t)l * 3 * EE,
                                   bqkv + (size_t)l * 3 * EE, nullptr, qkv, TT, 3 * EE, EE);

        attn_kernel<<<dim3(TT / 64, HH), 128>>>(qkv, qkv + EE, qkv + 2 * EE, att, 3 * EE);

        quantw_kernel<EE><<<(TT + 7) / 8, 256>>>(att, aq, sa, TT, 0, 0, TT);
        igemm<128, 128, 256, 2, 1>(aq, woq + wo_off, sa, swo + (size_t)l * EE,
                                   bo + (size_t)l * EE, x, x, TT, EE, EE);

        // ---- FFN block ----
        ln_quant_kernel<<<TT, 256>>>(x, ln2g + (size_t)l * EE, ln2b + (size_t)l * EE, aq, sa);
        igemm<256, 128, 512, 3, 1>(aq, w1q + w1_off, sa, sw1 + (size_t)l * FFD,
                                   b1 + (size_t)l * FFD, nullptr, f, TT, FFD, EE);

        quantw_kernel<FFD><<<(TT + 7) / 8, 256>>>(f, fq, sf, TT, 0, 0, TT);
        igemm<128, 128, 256, 2, 1>(fq, w2q + w2_off, sf, sw2 + (size_t)l * EE,
                                   b2 + (size_t)l * EE, x, x, TT, EE, FFD);
    }

    ln_quant_kernel<<<TT, 256>>>(x, lnfg, lnfb, aq, sa);
    igemm<256, 128, 512, 0, 1>(aq, whq, sa, swh, nullptr, nullptr, out, TT, VV, EE);
}

// round 11
// speedup vs baseline: 2.2181x; 2.2181x over previous
#include <cuda_runtime.h>
#include <math.h>
#include <stdint.h>

// Problem constants
#define TT  2048
#define EE  1024
#define HH  16
#define DHD 64
#define FFD 4096
#define VV  32000
#define NL  4

#define INV254 (1.0f / 254.0f)

// ---------------------------------------------------------------------------
// Scratch (device globals)
// ---------------------------------------------------------------------------
__device__ __align__(128) float g_x   [TT * EE];
__device__ __align__(128) float g_qkv [TT * 3 * EE];
__device__ __align__(128) float g_att [TT * EE];
__device__ __align__(128) float g_f   [TT * FFD];
__device__ __align__(128) float g_bqkv[NL * 3 * EE];

__device__ __align__(128) int8_t g_aq [TT * 2 * EE];     // act hi|lo (pitch 2E)
__device__ __align__(128) int8_t g_fq [TT * 2 * FFD];
__device__ float g_sa[TT];
__device__ float g_sf[TT];

__device__ __align__(128) int8_t g_wqkvq[(size_t)NL * 3 * EE * 2 * EE];
__device__ __align__(128) int8_t g_woq  [(size_t)NL * EE * 2 * EE];
__device__ __align__(128) int8_t g_w1q  [(size_t)NL * FFD * 2 * EE];
__device__ __align__(128) int8_t g_w2q  [(size_t)NL * EE * 2 * FFD];
__device__ __align__(128) int8_t g_whq  [(size_t)VV * 2 * EE];
__device__ float g_sqkv[NL * 3 * EE];
__device__ float g_swo [NL * EE];
__device__ float g_sw1 [NL * FFD];
__device__ float g_sw2 [NL * EE];
__device__ float g_swh [VV];

// ---------------------------------------------------------------------------
// Helpers
// ---------------------------------------------------------------------------
__device__ __forceinline__ uint32_t smem_u32(const void* p) {
    uint32_t a;
    asm("{ .reg .u64 t; cvta.to.shared.u64 t, %1; cvt.u32.u64 %0, t; }" : "=r"(a) : "l"(p));
    return a;
}

#define CP_ASYNC16(saddr, gptr) \
    asm volatile("cp.async.cg.shared.global [%0], [%1], 16;" \
        :: "r"(saddr), "l"(gptr) : "memory")
#define CP_COMMIT() asm volatile("cp.async.commit_group;" ::: "memory")
#define CP_WAIT(N)  asm volatile("cp.async.wait_group %0;" :: "n"(N) : "memory")

#define LDSM4(r0, r1, r2, r3, addr) \
    asm volatile("ldmatrix.sync.aligned.m8n8.x4.shared.b16 {%0,%1,%2,%3}, [%4];" \
        : "=r"(r0), "=r"(r1), "=r"(r2), "=r"(r3) : "r"(addr))

#define MMAS8(d, a, b) \
    asm volatile("mma.sync.aligned.m16n8k32.row.col.s32.s8.s8.s32 " \
        "{%0,%1,%2,%3}, {%4,%5,%6,%7}, {%8,%9}, {%0,%1,%2,%3};" \
        : "+r"((d)[0]), "+r"((d)[1]), "+r"((d)[2]), "+r"((d)[3]) \
        : "r"((a)[0]), "r"((a)[1]), "r"((a)[2]), "r"((a)[3]), \
          "r"((b)[0]), "r"((b)[1]))

__device__ __forceinline__ float gelu_erf(float v) {
    return 0.5f * v * (1.0f + erff(v * 0.70710678118654752f));
}

__device__ __forceinline__ float block_max(float v, float* sm8) {
    #pragma unroll
    for (int off = 16; off > 0; off >>= 1)
        v = fmaxf(v, __shfl_xor_sync(0xffffffffu, v, off));
    int w = threadIdx.x >> 5;
    if ((threadIdx.x & 31) == 0) sm8[w] = v;
    __syncthreads();
    float r = fmaxf(fmaxf(fmaxf(sm8[0], sm8[1]), fmaxf(sm8[2], sm8[3])),
                    fmaxf(fmaxf(sm8[4], sm8[5]), fmaxf(sm8[6], sm8[7])));
    return r;
}

__device__ __forceinline__ void quant4(float4 v, float invs, char4& hi, char4& lo) {
    float q0 = rintf(v.x * invs), q1 = rintf(v.y * invs);
    float q2 = rintf(v.z * invs), q3 = rintf(v.w * invs);
    hi = make_char4((char)(int)q0, (char)(int)q1, (char)(int)q2, (char)(int)q3);
    lo = make_char4((char)(int)rintf((v.x * invs - q0) * 254.0f),
                    (char)(int)rintf((v.y * invs - q1) * 254.0f),
                    (char)(int)rintf((v.z * invs - q2) * 254.0f),
                    (char)(int)rintf((v.w * invs - q3) * 254.0f));
}

// ---------------------------------------------------------------------------
// Embedding
// ---------------------------------------------------------------------------
__global__ void embed_kernel(const int* __restrict__ ids,
                             const float* __restrict__ tok,
                             const float* __restrict__ pos,
                             float* __restrict__ x) {
    int t = blockIdx.x;
    int c = threadIdx.x * 4;
    int id = ids[t];
    float4 a = *(const float4*)(tok + (size_t)id * EE + c);
    float4 b = *(const float4*)(pos + (size_t)t * EE + c);
    a.x += b.x; a.y += b.y; a.z += b.z; a.w += b.w;
    *(float4*)(x + (size_t)t * EE + c) = a;
}

// ---------------------------------------------------------------------------
// LayerNorm fused with 2-digit int8 row quantization.
// ---------------------------------------------------------------------------
__global__ void ln_quant_kernel(const float* __restrict__ x,
                                const float* __restrict__ g,
                                const float* __restrict__ b,
                                int8_t* __restrict__ out,
                                float* __restrict__ scale) {
    int t = blockIdx.x;
    int c = threadIdx.x * 4;
    float4 v4 = *(const float4*)(x + (size_t)t * EE + c);
    float s = v4.x + v4.y + v4.z + v4.w;
    float q = v4.x * v4.x + v4.y * v4.y + v4.z * v4.z + v4.w * v4.w;
    #pragma unroll
    for (int off = 16; off > 0; off >>= 1) {
        s += __shfl_down_sync(0xffffffffu, s, off);
        q += __shfl_down_sync(0xffffffffu, q, off);
    }
    __shared__ float ss[8], qq[8], mm[8];
    __shared__ float mean_s, rstd_s;
    int w = threadIdx.x >> 5, lane = threadIdx.x & 31;
    if (lane == 0) { ss[w] = s; qq[w] = q; }
    __syncthreads();
    if (threadIdx.x == 0) {
        float S = 0.f, Q = 0.f;
        #pragma unroll
        for (int i = 0; i < 8; i++) { S += ss[i]; Q += qq[i]; }
        float m = S * (1.0f / EE);
        float var = Q * (1.0f / EE) - m * m;
        mean_s = m;
        rstd_s = rsqrtf(var + 1e-5f);
    }
    __syncthreads();
    float m = mean_s, r = rstd_s;
    float4 gg = *(const float4*)(g + c);
    float4 bb = *(const float4*)(b + c);
    float4 o;
    o.x = (v4.x - m) * r * gg.x + bb.x;
    o.y = (v4.y - m) * r * gg.y + bb.y;
    o.z = (v4.z - m) * r * gg.z + bb.z;
    o.w = (v4.w - m) * r * gg.w + bb.w;
    float amax = fmaxf(fmaxf(fabsf(o.x), fabsf(o.y)), fmaxf(fabsf(o.z), fabsf(o.w)));
    amax = fmaxf(block_max(amax, mm), 1e-20f);
    float invs = 127.0f / amax;
    char4 hi, lo;
    quant4(o, invs, hi, lo);
    int8_t* d = out + (size_t)t * 2 * EE;
    *(char4*)(d + c) = hi;
    *(char4*)(d + EE + c) = lo;
    if (threadIdx.x == 0) scale[t] = amax * (1.0f / 127.0f);
}

// ---------------------------------------------------------------------------
// Warp-per-row 2-digit int8 quantization (weights or activations).
// ---------------------------------------------------------------------------
template <int K>
__global__ void quantw_kernel(const float* __restrict__ src,
                              int8_t* __restrict__ dst,
                              float* __restrict__ scale,
                              int rowsPerL, int dstStrideL, int dstOff,
                              int totalRows) {
    int row = blockIdx.x * 8 + (threadIdx.x >> 5);
    if (row >= totalRows) return;
    int lane = threadIdx.x & 31;
    int l = row / rowsPerL;
    int e = row - l * rowsPerL;
    size_t drow = (size_t)l * dstStrideL + dstOff + e;
    const float* sp = src + (size_t)row * K;
    constexpr int NV = K / 128;

    float amax = 0.f;
    #pragma unroll 4
    for (int i = 0; i < NV; i++) {
        float4 v = *(const float4*)(sp + (size_t)(lane + i * 32) * 4);
        amax = fmaxf(amax, fmaxf(fmaxf(fabsf(v.x), fabsf(v.y)),
                                 fmaxf(fabsf(v.z), fabsf(v.w))));
    }
    #pragma unroll
    for (int off = 16; off > 0; off >>= 1)
        amax = fmaxf(amax, __shfl_xor_sync(0xffffffffu, amax, off));
    amax = fmaxf(amax, 1e-20f);
    float invs = 127.0f / amax;

    int8_t* d = dst + drow * (size_t)(2 * K);
    #pragma unroll 4
    for (int i = 0; i < NV; i++) {
        int c = (lane + i * 32) * 4;
        float4 v = *(const float4*)(sp + c);
        char4 hi, lo;
        quant4(v, invs, hi, lo);
        *(char4*)(d + c) = hi;
        *(char4*)(d + K + c) = lo;
    }
    if (lane == 0) scale[drow] = amax * (1.0f / 127.0f);
}

__global__ void pack_bias_kernel(const float* __restrict__ bq,
                                 const float* __restrict__ bk,
                                 const float* __restrict__ bv,
                                 float* __restrict__ dst) {
    int i = blockIdx.x * 256 + threadIdx.x;
    if (i >= NL * 3 * EE) return;
    int l = i / (3 * EE);
    int r = i - l * 3 * EE;
    float v = (r < EE) ? bq[l * EE + r]
            : (r < 2 * EE) ? bk[l * EE + r - EE]
            : bv[l * EE + r - 2 * EE];
    dst[i] = v;
}

// ---------------------------------------------------------------------------
// int8 fully-fused NT GEMM via mma.sync m16n8k32:
//   per k-chunk, slot holds {A_hi, A_lo, B_hi, B_lo} loaded ONCE; computes
//   acc1 += Ah*Bh, acc2 += Ah*Bl, acc2 += Al*Bh.
//   C = sA[m]*sB[n]*(acc1 + acc2/254)  (+ epilogue)
// BM=BN=128, 256 threads, 3 slots, stride 144.
// EPI: 0 none, 1 +bias, 2 +bias+res, 3 +bias then erf-GELU
// ---------------------------------------------------------------------------
template <int BM, int BN, int EPI>
__global__ void __launch_bounds__(256, 1)
igemm_kernel(const int8_t* __restrict__ A,
             const int8_t* __restrict__ B,
             const float* __restrict__ sAv,
             const float* __restrict__ sBv,
             const float* __restrict__ bias,
             const float* __restrict__ res,
             float* __restrict__ C,
             int K, int ldc) {
    constexpr int WM = BM / 2;         // 64
    constexpr int MT = WM / 16;        // 4
    constexpr int WN = BN / 4;         // 32
    constexpr int NT = WN / 8;         // 4
    constexpr int STRIDE = 144;
    constexpr int BLK = BM * STRIDE;   // one digit-block of A (= BN*STRIDE for B)
    constexpr int SLOT = 2 * BM * STRIDE + 2 * BN * STRIDE;

    extern __shared__ char smem[];
    const uint32_t sbase = smem_u32(smem);
    const int tid = threadIdx.x;
    const int wid = tid >> 5;
    const int lane = tid & 31;
    const int warp_m = wid & 1;
    const int warp_n = wid >> 1;
    const int brow = blockIdx.x * BM;
    const int bcol = blockIdx.y * BN;
    const int K2 = 2 * K;
    const int nKp = K >> 7;            // 128-byte chunks

    int acc1[MT][NT][4];
    int acc2[MT][NT][4];
    #pragma unroll
    for (int mt = 0; mt < MT; mt++)
        #pragma unroll
        for (int nt = 0; nt < NT; nt++)
            #pragma unroll
            for (int e = 0; e < 4; e++) { acc1[mt][nt][e] = 0; acc2[mt][nt][e] = 0; }

    // Load one k-chunk: A_hi, A_lo, B_hi, B_lo (each BM/BN rows x 128 bytes)
    auto load_chunk = [&](int slot, int kc) {
        uint32_t s0 = sbase + slot * SLOT;
        int off = kc * 128;
        #pragma unroll
        for (int i = 0; i < BM / 32; i++) {          // A_hi
            int c = tid + i * 256;
            int r = c >> 3, k8 = c & 7;
            CP_ASYNC16(s0 + r * STRIDE + k8 * 16,
                       A + (size_t)(brow + r) * K2 + off + k8 * 16);
        }
        uint32_t sAl = s0 + BLK;
        #pragma unroll
        for (int i = 0; i < BM / 32; i++) {          // A_lo
            int c = tid + i * 256;
            int r = c >> 3, k8 = c & 7;
            CP_ASYNC16(sAl + r * STRIDE + k8 * 16,
                       A + (size_t)(brow + r) * K2 + K + off + k8 * 16);
        }
        uint32_t sBh = s0 + 2 * BLK;
        #pragma unroll
        for (int i = 0; i < BN / 32; i++) {          // B_hi
            int c = tid + i * 256;
            int r = c >> 3, k8 = c & 7;
            CP_ASYNC16(sBh + r * STRIDE + k8 * 16,
                       B + (size_t)(bcol + r) * K2 + off + k8 * 16);
        }
        uint32_t sBl = s0 + 2 * BLK + BN * STRIDE;
        #pragma unroll
        for (int i = 0; i < BN / 32; i++) {          // B_lo
            int c = tid + i * 256;
            int r = c >> 3, k8 = c & 7;
            CP_ASYNC16(sBl + r * STRIDE + k8 * 16,
                       B + (size_t)(bcol + r) * K2 + K + off + k8 * 16);
        }
        CP_COMMIT();
    };

    load_chunk(0, 0);
    if (nKp > 1) load_chunk(1, 1); else CP_COMMIT();

    int st = 0;
    for (int kc = 0; kc < nKp; kc++) {
        CP_WAIT(1);
        __syncthreads();
        const uint32_t s0 = sbase + st * SLOT;
        const uint32_t aRow = (uint32_t)(warp_m * WM + (lane & 15)) * STRIDE
                            + (uint32_t)(lane >> 4) * 16;
        const uint32_t bRow = (uint32_t)(warp_n * WN + ((lane >> 4) << 3) + (lane & 7)) * STRIDE
                            + (uint32_t)((lane >> 3) & 1) * 16;
        const uint32_t aHi = s0 + aRow;
        const uint32_t aLo = aHi + BLK;
        const uint32_t bHi = s0 + 2 * BLK + bRow;
        const uint32_t bLo = bHi + BN * STRIDE;

        if (kc + 2 < nKp) {
            int st2 = st + 2; if (st2 >= 3) st2 -= 3;
            load_chunk(st2, kc + 2);
        } else {
            CP_COMMIT();
        }

        #pragma unroll
        for (int ks = 0; ks < 4; ks++) {
            const uint32_t ko = (uint32_t)(ks * 32);
            uint32_t afh[MT][4];
            #pragma unroll
            for (int mt = 0; mt < MT; mt++)
                LDSM4(afh[mt][0], afh[mt][1], afh[mt][2], afh[mt][3],
                      aHi + (uint32_t)(mt * 16 * STRIDE) + ko);
            uint32_t bfh[NT][2];
            #pragma unroll
            for (int p = 0; p < NT / 2; p++) {
                uint32_t r0, r1, r2, r3;
                LDSM4(r0, r1, r2, r3, bHi + (uint32_t)(p * 16 * STRIDE) + ko);
                bfh[2 * p][0] = r0; bfh[2 * p][1] = r1;
                bfh[2 * p + 1][0] = r2; bfh[2 * p + 1][1] = r3;
            }
            // acc1 += Ah * Bh
            #pragma unroll
            for (int mt = 0; mt < MT; mt++)
                #pragma unroll
                for (int nt = 0; nt < NT; nt++)
                    MMAS8(acc1[mt][nt], afh[mt], bfh[nt]);
            // acc2 += Ah * Bl
            {
                uint32_t bfl[NT][2];
                #pragma unroll
                for (int p = 0; p < NT / 2; p++) {
                    uint32_t r0, r1, r2, r3;
                    LDSM4(r0, r1, r2, r3, bLo + (uint32_t)(p * 16 * STRIDE) + ko);
                    bfl[2 * p][0] = r0; bfl[2 * p][1] = r1;
                    bfl[2 * p + 1][0] = r2; bfl[2 * p + 1][1] = r3;
                }
                #pragma unroll
                for (int mt = 0; mt < MT; mt++)
                    #pragma unroll
                    for (int nt = 0; nt < NT; nt++)
                        MMAS8(acc2[mt][nt], afh[mt], bfl[nt]);
            }
            // acc2 += Al * Bh
            {
                uint32_t afl[MT][4];
                #pragma unroll
                for (int mt = 0; mt < MT; mt++)
                    LDSM4(afl[mt][0], afl[mt][1], afl[mt][2], afl[mt][3],
                          aLo + (uint32_t)(mt * 16 * STRIDE) + ko);
                #pragma unroll
                for (int mt = 0; mt < MT; mt++)
                    #pragma unroll
                    for (int nt = 0; nt < NT; nt++)
                        MMAS8(acc2[mt][nt], afl[mt], bfh[nt]);
            }
        }

        st++; if (st == 3) st = 0;
    }

    // ---- epilogue ----
    #pragma unroll
    for (int mt = 0; mt < MT; mt++) {
        const int r0 = brow + warp_m * WM + mt * 16 + (lane >> 2);
        const float sa0 = sAv[r0];
        const float sa1 = sAv[r0 + 8];
        #pragma unroll
        for (int nt = 0; nt < NT; nt++) {
            const int col = bcol + warp_n * WN + nt * 8 + ((lane & 3) << 1);
            float2 sb = *(const float2*)(sBv + col);
            float2 v0, v1;
            v0.x = ((float)acc1[mt][nt][0] + (float)acc2[mt][nt][0] * INV254) * sa0 * sb.x;
            v0.y = ((float)acc1[mt][nt][1] + (float)acc2[mt][nt][1] * INV254) * sa0 * sb.y;
            v1.x = ((float)acc1[mt][nt][2] + (float)acc2[mt][nt][2] * INV254) * sa1 * sb.x;
            v1.y = ((float)acc1[mt][nt][3] + (float)acc2[mt][nt][3] * INV254) * sa1 * sb.y;
            if (EPI >= 1) {
                float2 bb = *(const float2*)(bias + col);
                v0.x += bb.x; v0.y += bb.y;
                v1.x += bb.x; v1.y += bb.y;
            }
            if (EPI == 2) {
                float2 q0 = *(const float2*)(res + (size_t)r0 * ldc + col);
                float2 q1 = *(const float2*)(res + (size_t)(r0 + 8) * ldc + col);
                v0.x += q0.x; v0.y += q0.y;
                v1.x += q1.x; v1.y += q1.y;
            }
            if (EPI == 3) {
                v0.x = gelu_erf(v0.x); v0.y = gelu_erf(v0.y);
                v1.x = gelu_erf(v1.x); v1.y = gelu_erf(v1.y);
            }
            *(float2*)(C + (size_t)r0 * ldc + col) = v0;
            *(float2*)(C + (size_t)(r0 + 8) * ldc + col) = v1;
        }
    }
}

// ---------------------------------------------------------------------------
// Fused causal attention v2 (KV-split halves), fp32 in/out.
// ---------------------------------------------------------------------------
__global__ void __launch_bounds__(128)
attn_kernel(const float* __restrict__ q,
            const float* __restrict__ k,
            const float* __restrict__ v,
            float* __restrict__ o, int qp) {
    __shared__ float Ks[2][16][64];
    __shared__ float Vs[2][16][64];
    __shared__ float comb[64][66];

    const int h    = blockIdx.y;
    const int qt   = (int)gridDim.x - 1 - blockIdx.x;
    const int half = threadIdx.x >> 6;
    const int lt   = threadIdx.x & 63;
    const int iq   = qt * 64 + lt;
    const float scale = 0.125f;

    const int nTiles = qt * 4 + 4;
    const int split  = nTiles >> 1;
    const int t0 = half ? split : 0;
    const int t1 = half ? nTiles : split;

    float qr[64];
    {
        const float* qptr = q + (size_t)iq * qp + h * DHD;
        #pragma unroll
        for (int d = 0; d < 64; d += 4) {
            float4 t4 = *(const float4*)(qptr + d);
            qr[d] = t4.x; qr[d + 1] = t4.y; qr[d + 2] = t4.z; qr[d + 3] = t4.w;
        }
    }

    float m = -INFINITY, l = 0.0f;
    float oacc[64];
    #pragma unroll
    for (int d = 0; d < 64; d++) oacc[d] = 0.0f;

    for (int tile = t0; tile < t1; tile++) {
        const int jt = tile * 16;
        #pragma unroll
        for (int pp = 0; pp < 4; pp++) {
            int f  = lt + pp * 64;
            int r  = f >> 4;
            int c4 = (f & 15) << 2;
            *(float4*)&Ks[half][r][c4] = *(const float4*)(k + (size_t)(jt + r) * qp + h * DHD + c4);
            *(float4*)&Vs[half][r][c4] = *(const float4*)(v + (size_t)(jt + r) * qp + h * DHD + c4);
        }
        asm volatile("bar.sync %0, 64;" :: "r"(1 + half) : "memory");

        if (jt <= iq) {
            float s[16];
            #pragma unroll
            for (int jj = 0; jj < 16; jj++) {
                float s0 = 0.f, s1 = 0.f, s2 = 0.f, s3 = 0.f;
                #pragma unroll
                for (int d4 = 0; d4 < 16; d4++) {
                    float4 kv = *(const float4*)&Ks[half][jj][d4 * 4];
                    s0 += qr[d4 * 4 + 0] * kv.x;
                    s1 += qr[d4 * 4 + 1] * kv.y;
                    s2 += qr[d4 * 4 + 2] * kv.z;
                    s3 += qr[d4 * 4 + 3] * kv.w;
                }
                float sv = (s0 + s1) + (s2 + s3);
                s[jj] = (jt + jj <= iq) ? sv * scale : -INFINITY;
            }
            float tm = s[0];
            #pragma unroll
            for (int jj = 1; jj < 16; jj++) tm = fmaxf(tm, s[jj]);
            float nm = fmaxf(m, tm);
            float corr = __expf(m - nm);
            l *= corr;
            #pragma unroll
            for (int d = 0; d < 64; d++) oacc[d] *= corr;
            #pragma unroll
            for (int jj = 0; jj < 16; jj++) {
                float pwt = __expf(s[jj] - nm);
                l += pwt;
                #pragma unroll
                for (int d4 = 0; d4 < 16; d4++) {
                    float4 vv = *(const float4*)&Vs[half][jj][d4 * 4];
                    oacc[d4 * 4 + 0] += pwt * vv.x;
                    oacc[d4 * 4 + 1] += pwt * vv.y;
                    oacc[d4 * 4 + 2] += pwt * vv.z;
                    oacc[d4 * 4 + 3] += pwt * vv.w;
                }
            }
            m = nm;
        }
        asm volatile("bar.sync %0, 64;" :: "r"(1 + half) : "memory");
    }

    if (half) {
        #pragma unroll
        for (int d = 0; d < 64; d++) comb[lt][d] = oacc[d];
        comb[lt][64] = m;
        comb[lt][65] = l;
    }
    __syncthreads();
    if (!half) {
        float m1 = comb[lt][64], l1 = comb[lt][65];
        float nm = fmaxf(m, m1);
        float c0 = __expf(m - nm);
        float c1 = __expf(m1 - nm);
        float inv = 1.0f / (l * c0 + l1 * c1);
        float* optr = o + (size_t)iq * EE + h * DHD;
        #pragma unroll
        for (int d = 0; d < 64; d += 4) {
            float4 t4;
            t4.x = (oacc[d]     * c0 + comb[lt][d]     * c1) * inv;
            t4.y = (oacc[d + 1] * c0 + comb[lt][d + 1] * c1) * inv;
            t4.z = (oacc[d + 2] * c0 + comb[lt][d + 2] * c1) * inv;
            t4.w = (oacc[d + 3] * c0 + comb[lt][d + 3] * c1) * inv;
            *(float4*)(optr + d) = t4;
        }
    }
}

// ---------------------------------------------------------------------------
// Host-side launch sequence
// ---------------------------------------------------------------------------
template <int BM, int BN, int EPI>
static inline void igemm(const int8_t* A, const int8_t* B,
                         const float* sA, const float* sB,
                         const float* bias, const float* res, float* C,
                         int M, int N, int K) {
    constexpr int SMEM = 3 * 2 * (BM + BN) * 144;
    dim3 grid(M / BM, N / BN);
    igemm_kernel<BM, BN, EPI><<<grid, 256, SMEM>>>(A, B, sA, sB, bias, res, C, K, N);
}

extern "C" void kernel_launch(void* const* d_in, const int* in_sizes, int n_in,
                              void* d_out, int out_size) {
    const int*   ids  = (const int*)  d_in[0];
    const float* tok  = (const float*)d_in[1];
    const float* pos  = (const float*)d_in[2];
    const float* Wq   = (const float*)d_in[3];
    const float* bq   = (const float*)d_in[4];
    const float* Wk   = (const float*)d_in[5];
    const float* bk   = (const float*)d_in[6];
    const float* Wv   = (const float*)d_in[7];
    const float* bv   = (const float*)d_in[8];
    const float* Wo   = (const float*)d_in[9];
    const float* bo   = (const float*)d_in[10];
    const float* ln1g = (const float*)d_in[11];
    const float* ln1b = (const float*)d_in[12];
    const float* W1   = (const float*)d_in[13];
    const float* b1   = (const float*)d_in[14];
    const float* W2   = (const float*)d_in[15];
    const float* b2   = (const float*)d_in[16];
    const float* ln2g = (const float*)d_in[17];
    const float* ln2b = (const float*)d_in[18];
    const float* lnfg = (const float*)d_in[19];
    const float* lnfb = (const float*)d_in[20];
    const float* Wh   = (const float*)d_in[21];
    float* out = (float*)d_out;

    // 3 slots x 2*(128+128)*144 = 221184 B
    cudaFuncSetAttribute(igemm_kernel<128, 128, 0>, cudaFuncAttributeMaxDynamicSharedMemorySize, 221184);
    cudaFuncSetAttribute(igemm_kernel<128, 128, 1>, cudaFuncAttributeMaxDynamicSharedMemorySize, 221184);
    cudaFuncSetAttribute(igemm_kernel<128, 128, 2>, cudaFuncAttributeMaxDynamicSharedMemorySize, 221184);
    cudaFuncSetAttribute(igemm_kernel<128, 128, 3>, cudaFuncAttributeMaxDynamicSharedMemorySize, 221184);

    float *x, *qkv, *att, *f, *bqkv, *sa, *sf;
    float *sqkv, *swo, *sw1, *sw2, *swh;
    int8_t *aq, *fq, *wqkvq, *woq, *w1q, *w2q, *whq;
    cudaGetSymbolAddress((void**)&x,     g_x);
    cudaGetSymbolAddress((void**)&qkv,   g_qkv);
    cudaGetSymbolAddress((void**)&att,   g_att);
    cudaGetSymbolAddress((void**)&f,     g_f);
    cudaGetSymbolAddress((void**)&bqkv,  g_bqkv);
    cudaGetSymbolAddress((void**)&aq,    g_aq);
    cudaGetSymbolAddress((void**)&fq,    g_fq);
    cudaGetSymbolAddress((void**)&sa,    g_sa);
    cudaGetSymbolAddress((void**)&sf,    g_sf);
    cudaGetSymbolAddress((void**)&wqkvq, g_wqkvq);
    cudaGetSymbolAddress((void**)&woq,   g_woq);
    cudaGetSymbolAddress((void**)&w1q,   g_w1q);
    cudaGetSymbolAddress((void**)&w2q,   g_w2q);
    cudaGetSymbolAddress((void**)&whq,   g_whq);
    cudaGetSymbolAddress((void**)&sqkv,  g_sqkv);
    cudaGetSymbolAddress((void**)&swo,   g_swo);
    cudaGetSymbolAddress((void**)&sw1,   g_sw1);
    cudaGetSymbolAddress((void**)&sw2,   g_sw2);
    cudaGetSymbolAddress((void**)&swh,   g_swh);

    // ---- up-front weight quantization (warp-per-row) ----
    quantw_kernel<EE><<<(NL * EE + 7) / 8, 256>>>(Wq, wqkvq, sqkv, EE, 3 * EE, 0, NL * EE);
    quantw_kernel<EE><<<(NL * EE + 7) / 8, 256>>>(Wk, wqkvq, sqkv, EE, 3 * EE, EE, NL * EE);
    quantw_kernel<EE><<<(NL * EE + 7) / 8, 256>>>(Wv, wqkvq, sqkv, EE, 3 * EE, 2 * EE, NL * EE);
    quantw_kernel<EE><<<(NL * EE + 7) / 8, 256>>>(Wo, woq, swo, NL * EE, 0, 0, NL * EE);
    quantw_kernel<EE><<<(NL * FFD + 7) / 8, 256>>>(W1, w1q, sw1, NL * FFD, 0, 0, NL * FFD);
    quantw_kernel<FFD><<<(NL * EE + 7) / 8, 256>>>(W2, w2q, sw2, NL * EE, 0, 0, NL * EE);
    quantw_kernel<EE><<<(VV + 7) / 8, 256>>>(Wh, whq, swh, VV, 0, 0, VV);
    pack_bias_kernel<<<(NL * 3 * EE + 255) / 256, 256>>>(bq, bk, bv, bqkv);

    embed_kernel<<<TT, 256>>>(ids, tok, pos, x);

    for (int l = 0; l < NL; l++) {
        const size_t wq_off = (size_t)l * 3 * EE * 2 * EE;
        const size_t wo_off = (size_t)l * EE * 2 * EE;
        const size_t w1_off = (size_t)l * FFD * 2 * EE;
        const size_t w2_off = (size_t)l * EE * 2 * FFD;

        // ---- attention block ----
        ln_quant_kernel<<<TT, 256>>>(x, ln1g + (size_t)l * EE, ln1b + (size_t)l * EE, aq, sa);
        igemm<128, 128, 1>(aq, wqkvq + wq_off, sa, sqkv + (size_t)l * 3 * EE,
                           bqkv + (size_t)l * 3 * EE, nullptr, qkv, TT, 3 * EE, EE);

        attn_kernel<<<dim3(TT / 64, HH), 128>>>(qkv, qkv + EE, qkv + 2 * EE, att, 3 * EE);

        quantw_kernel<EE><<<(TT + 7) / 8, 256>>>(att, aq, sa, TT, 0, 0, TT);
        igemm<128, 128, 2>(aq, woq + wo_off, sa, swo + (size_t)l * EE,
                           bo + (size_t)l * EE, x, x, TT, EE, EE);

        // ---- FFN block ----
        ln_quant_kernel<<<TT, 256>>>(x, ln2g + (size_t)l * EE, ln2b + (size_t)l * EE, aq, sa);
        igemm<128, 128, 3>(aq, w1q + w1_off, sa, sw1 + (size_t)l * FFD,
                           b1 + (size_t)l * FFD, nullptr, f, TT, FFD, EE);

        quantw_kernel<FFD><<<(TT + 7) / 8, 256>>>(f, fq, sf, TT, 0, 0, TT);
        igemm<128, 128, 2>(fq, w2q + w2_off, sf, sw2 + (size_t)l * EE,
                           b2 + (size_t)l * EE, x, x, TT, EE, FFD);
    }

    ln_quant_kernel<<<TT, 256>>>(x, lnfg, lnfb, aq, sa);
    igemm<128, 128, 0>(aq, whq, sa, swh, nullptr, nullptr, out, TT, VV, EE);
}